// round 1
// baseline (speedup 1.0000x reference)
#include <cuda_runtime.h>
#include <cuda_bf16.h>

// Problem constants
#define B_  256
#define C_  64
#define T_  406
#define D_  10
#define TD  4060          // T*D
#define KP  4608          // padded K: [0,4060)=m*wn*x | [4060,4466)=mask | [4466,4608)=0
#define SPLITK 9
#define KCH 512           // KP / SPLITK
#define BM  16            // b-rows per block
#define MT  16            // B_/BM m-tiles

// Output offsets (floats), tuple order: output_seq, input_seq, loss, indices, label, mask, proto_count
#define O_OUT  0
#define O_IN   1039360
#define O_LOSS 2078720
#define O_IDX  2095104
#define O_LAB  2095360
#define O_MASK 2095616
#define O_PC   2199552

// Static scratch (no allocation allowed)
__device__ __align__(16) float g_wn[4064];
__device__ __align__(16) float g_Y[B_ * KP];          // 4.72 MB
__device__ __align__(16) float g_P[C_ * KP];          // 1.18 MB
__device__ float g_part[SPLITK * B_ * C_];            // 0.59 MB
__device__ float g_S1[B_];

// ---------------------------------------------------------------------------
// Kernel 1: softplus-normalized weights  wn = softplus(w) / sum(softplus(w))
// One block.
// ---------------------------------------------------------------------------
__global__ void wn_kernel(const float* __restrict__ w) {
    __shared__ float red[32];
    int tid = threadIdx.x;
    float s = 0.f;
    for (int k = tid; k < TD; k += blockDim.x) {
        float x = w[k];
        // jax softplus: max(x,0) + log1p(exp(-|x|))
        float sp = fmaxf(x, 0.f) + log1pf(expf(-fabsf(x)));
        g_wn[k] = sp;
        s += sp;
    }
    // block reduce
    for (int o = 16; o; o >>= 1) s += __shfl_xor_sync(0xffffffffu, s, o);
    if ((tid & 31) == 0) red[tid >> 5] = s;
    __syncthreads();
    int nw = blockDim.x >> 5;
    if (tid < 32) {
        float v = (tid < nw) ? red[tid] : 0.f;
        for (int o = 16; o; o >>= 1) v += __shfl_xor_sync(0xffffffffu, v, o);
        if (tid == 0) red[0] = v;
    }
    __syncthreads();
    float inv = 1.f / red[0];
    for (int k = tid; k < TD; k += blockDim.x) g_wn[k] *= inv;
}

// ---------------------------------------------------------------------------
// Kernel 2: build P' rows: [p | -0.5*Q] with Q[c,t] = sum_d wn[t,d]*p^2
// grid = C_ blocks
// ---------------------------------------------------------------------------
__global__ void prepP_kernel(const float* __restrict__ proto) {
    int c = blockIdx.x, tid = threadIdx.x;
    const float4* src4 = (const float4*)(proto + (size_t)c * TD);
    float4* dst4 = (float4*)(g_P + (size_t)c * KP);
    for (int i = tid; i < TD / 4; i += blockDim.x) dst4[i] = src4[i];
    const float* pr = proto + (size_t)c * TD;
    for (int t = tid; t < T_; t += blockDim.x) {
        float q = 0.f;
        #pragma unroll
        for (int d = 0; d < D_; d++) {
            float pv = pr[t * D_ + d];
            q += g_wn[t * D_ + d] * pv * pv;
        }
        g_P[(size_t)c * KP + TD + t] = -0.5f * q;
    }
    for (int k = TD + T_ + tid; k < KP; k += blockDim.x)
        g_P[(size_t)c * KP + k] = 0.f;
}

// ---------------------------------------------------------------------------
// Kernel 3: build Y rows: [m*wn*x | m], and S1[b] = sum Y*x
// grid = B_ blocks
// ---------------------------------------------------------------------------
__global__ void prepY_kernel(const float* __restrict__ x, const float* __restrict__ mask) {
    __shared__ float red[32];
    int b = blockIdx.x, tid = threadIdx.x;
    const float* xr = x + (size_t)b * TD;
    const float* mr = mask + (size_t)b * T_;
    float* yr = g_Y + (size_t)b * KP;
    float s1 = 0.f;
    for (int k = tid; k < TD; k += blockDim.x) {
        float m = mr[k / D_];
        float xv = xr[k];
        float y = m * g_wn[k] * xv;
        yr[k] = y;
        s1 += y * xv;
    }
    for (int t = tid; t < T_; t += blockDim.x) yr[TD + t] = mr[t];
    for (int k = TD + T_ + tid; k < KP; k += blockDim.x) yr[k] = 0.f;
    // block reduce s1
    for (int o = 16; o; o >>= 1) s1 += __shfl_xor_sync(0xffffffffu, s1, o);
    if ((tid & 31) == 0) red[tid >> 5] = s1;
    __syncthreads();
    if (tid < 32) {
        float v = (tid < (int)(blockDim.x >> 5)) ? red[tid] : 0.f;
        for (int o = 16; o; o >>= 1) v += __shfl_xor_sync(0xffffffffu, v, o);
        if (tid == 0) g_S1[b] = v;
    }
}

// ---------------------------------------------------------------------------
// Kernel 4: split-K GEMM  part[s][b][c] = sum_{k in chunk s} Y[b][k]*P[c][k]
// grid = (MT, SPLITK), 256 threads (8 warps). Warp w handles c in [8w, 8w+8),
// all 16 b of the block's m-tile; lanes split K.
// ---------------------------------------------------------------------------
__global__ void __launch_bounds__(256, 1) gemm_kernel() {
    int warp = threadIdx.x >> 5, lane = threadIdx.x & 31;
    int bm0 = blockIdx.x * BM;
    int c0  = warp * 8;
    int kbase = blockIdx.y * KCH + lane;

    float acc[BM][8];
    #pragma unroll
    for (int i = 0; i < BM; i++)
        #pragma unroll
        for (int j = 0; j < 8; j++) acc[i][j] = 0.f;

    const float* Yb = g_Y + (size_t)bm0 * KP;
    const float* Pb = g_P + (size_t)c0 * KP;

    #pragma unroll
    for (int s = 0; s < KCH / 32; s++) {
        int k = kbase + s * 32;
        float yv[BM], pv[8];
        #pragma unroll
        for (int i = 0; i < BM; i++) yv[i] = Yb[(size_t)i * KP + k];
        #pragma unroll
        for (int j = 0; j < 8; j++) pv[j] = Pb[(size_t)j * KP + k];
        #pragma unroll
        for (int i = 0; i < BM; i++) {
            float y = yv[i];
            #pragma unroll
            for (int j = 0; j < 8; j++) acc[i][j] = fmaf(y, pv[j], acc[i][j]);
        }
    }

    float* part = g_part + ((size_t)blockIdx.y * B_) * C_;
    #pragma unroll
    for (int i = 0; i < BM; i++) {
        #pragma unroll
        for (int j = 0; j < 8; j++) {
            float v = acc[i][j];
            for (int o = 16; o; o >>= 1) v += __shfl_xor_sync(0xffffffffu, v, o);
            if (lane == 0) part[(bm0 + i) * C_ + c0 + j] = v;
        }
    }
}

// ---------------------------------------------------------------------------
// Kernel 5: loss[b][c] = S1[b] - 2*sum_s part[s][b][c]   (fixed-order, deterministic)
// ---------------------------------------------------------------------------
__global__ void loss_kernel(float* __restrict__ out) {
    int idx = blockIdx.x * blockDim.x + threadIdx.x;   // < B_*C_
    int b = idx >> 6, c = idx & 63;
    float s = 0.f;
    #pragma unroll
    for (int sp = 0; sp < SPLITK; sp++) s += g_part[(sp * B_ + b) * C_ + c];
    out[O_LOSS + idx] = g_S1[b] - 2.f * s;
}

// ---------------------------------------------------------------------------
// Kernel 6: output_seq[b] = prototypes[label[b]]  (float4 gather)
// grid = B_ blocks
// ---------------------------------------------------------------------------
__global__ void gather_kernel(const float* __restrict__ proto, const int* __restrict__ label,
                              float* __restrict__ out) {
    int b = blockIdx.x;
    int lab = label[b];
    const float4* src = (const float4*)(proto + (size_t)lab * TD);
    float4* dst = (float4*)(out + O_OUT + (size_t)b * TD);
    for (int i = threadIdx.x; i < TD / 4; i += blockDim.x) dst[i] = src[i];
}

// ---------------------------------------------------------------------------
// Kernel 7: indices, label, proto_count  (one block, 256 threads = B_)
// ---------------------------------------------------------------------------
__global__ void misc_kernel(const int* __restrict__ label, const float* __restrict__ pc,
                            float* __restrict__ out) {
    __shared__ int cnt[C_];
    int tid = threadIdx.x;
    if (tid < C_) cnt[tid] = 0;
    __syncthreads();
    int lab = label[tid];
    out[O_IDX + tid] = (float)lab;   // K=1 -> indices == label
    out[O_LAB + tid] = (float)lab;
    atomicAdd(&cnt[lab], 1);
    __syncthreads();
    if (tid < C_) out[O_PC + tid] = pc[tid] + (float)cnt[tid];
}

// ---------------------------------------------------------------------------
extern "C" void kernel_launch(void* const* d_in, const int* in_sizes, int n_in,
                              void* d_out, int out_size) {
    const float* input_seq  = (const float*)d_in[0];
    const int*   label      = (const int*)  d_in[1];
    const float* mask       = (const float*)d_in[2];
    const float* prototypes = (const float*)d_in[3];
    const float* weights    = (const float*)d_in[4];
    const float* protocount = (const float*)d_in[5];
    float* out = (float*)d_out;

    wn_kernel<<<1, 1024>>>(weights);
    prepP_kernel<<<C_, 256>>>(prototypes);
    prepY_kernel<<<B_, 256>>>(input_seq, mask);
    gemm_kernel<<<dim3(MT, SPLITK), 256>>>();
    loss_kernel<<<(B_ * C_) / 256, 256>>>(out);

    gather_kernel<<<B_, 128>>>(prototypes, label, out);
    misc_kernel<<<1, B_>>>(label, protocount, out);
    cudaMemcpyAsync(out + O_IN,   input_seq, (size_t)B_ * TD * sizeof(float),
                    cudaMemcpyDeviceToDevice, 0);
    cudaMemcpyAsync(out + O_MASK, mask,      (size_t)B_ * T_ * sizeof(float),
                    cudaMemcpyDeviceToDevice, 0);
}

// round 2
// speedup vs baseline: 1.3855x; 1.3855x over previous
#include <cuda_runtime.h>
#include <cuda_bf16.h>

// Problem constants
#define B_  256
#define C_  64
#define T_  406
#define D_  10
#define TD  4060          // T*D
#define KP  4608          // padded K: [0,4060)=m*wn*x | [4060,4466)=mask | [4466,4608)=0
#define SPLITK 9
#define KCH 512           // KP / SPLITK

// Output offsets (floats): output_seq, input_seq, loss, indices, label, mask, proto_count
#define O_OUT  0
#define O_IN   1039360
#define O_LOSS 2078720
#define O_IDX  2095104
#define O_LAB  2095360
#define O_MASK 2095616
#define O_PC   2199552

// Static scratch
__device__ __align__(16) float g_sp[4064];            // softplus(w), unnormalized
__device__ float g_spsum[32];                          // partial sums of softplus
__device__ __align__(16) float g_Y[B_ * KP];          // 4.72 MB
__device__ __align__(16) float g_P[C_ * KP];          // 1.18 MB
__device__ float g_part[SPLITK * B_ * C_];            // 0.59 MB
__device__ float g_S1[B_];

// ---------------------------------------------------------------------------
// Kernel 0: softplus spread over 32 blocks. Each block writes its 128-elem
// chunk of g_sp and its partial sum to g_spsum. Consumers sum the 32 partials
// themselves (deterministic fixed order) -> no extra sync kernel.
// ---------------------------------------------------------------------------
__global__ void sp_kernel(const float* __restrict__ w) {
    __shared__ float red[4];
    int k = blockIdx.x * 128 + threadIdx.x;
    float sp = 0.f;
    if (k < TD) {
        float x = w[k];
        sp = fmaxf(x, 0.f) + log1pf(expf(-fabsf(x)));   // jax softplus
        g_sp[k] = sp;
    }
    for (int o = 16; o; o >>= 1) sp += __shfl_xor_sync(0xffffffffu, sp, o);
    if ((threadIdx.x & 31) == 0) red[threadIdx.x >> 5] = sp;
    __syncthreads();
    if (threadIdx.x == 0)
        g_spsum[blockIdx.x] = red[0] + red[1] + red[2] + red[3];
}

// ---------------------------------------------------------------------------
// Kernel A: fused prep.
//   blocks [0, 64):    build P' row c = [p | -0.5*inv*Q | 0]
//   blocks [64, 320):  build Y row b = [m*sp*inv*x | m | 0], S1[b],
//                      copy input_seq->out, mask->out, gather proto[label]->out,
//                      indices/label outputs
//   block 320:         proto_count
// ---------------------------------------------------------------------------
__global__ void __launch_bounds__(256) prep_kernel(
    const float* __restrict__ x, const int* __restrict__ label,
    const float* __restrict__ mask, const float* __restrict__ proto,
    const float* __restrict__ pcin, float* __restrict__ out)
{
    int bid = blockIdx.x, tid = threadIdx.x;
    float tot = 0.f;
    #pragma unroll
    for (int i = 0; i < 32; i++) tot += g_spsum[i];
    float inv = 1.f / tot;

    if (bid < C_) {
        // ---- P' row for class c ----
        int c = bid;
        const float* pr = proto + (size_t)c * TD;
        float* Pr = g_P + (size_t)c * KP;
        const float4* s4 = (const float4*)pr;
        float4* d4 = (float4*)Pr;
        for (int i = tid; i < TD / 4; i += 256) d4[i] = s4[i];
        for (int t = tid; t < T_; t += 256) {
            float q = 0.f;
            #pragma unroll
            for (int d = 0; d < D_; d++) {
                float pv = pr[t * D_ + d];
                q = fmaf(g_sp[t * D_ + d] * pv, pv, q);
            }
            Pr[TD + t] = -0.5f * inv * q;
        }
        for (int k = TD + T_ + tid; k < KP; k += 256) Pr[k] = 0.f;
    } else if (bid < C_ + B_) {
        // ---- Y row + copies + gather for sample b ----
        __shared__ float red[8];
        int b = bid - C_;
        const float* xr = x + (size_t)b * TD;
        const float* mr = mask + (size_t)b * T_;
        float* yr = g_Y + (size_t)b * KP;
        float* oin = out + O_IN + (size_t)b * TD;
        float s1 = 0.f;
        for (int k = tid; k < TD; k += 256) {
            float m  = mr[k / D_];
            float xv = xr[k];
            float y  = m * (g_sp[k] * inv) * xv;
            yr[k] = y;
            oin[k] = xv;                 // input_seq pass-through
            s1 = fmaf(y, xv, s1);
        }
        for (int t = tid; t < T_; t += 256) {
            float m = mr[t];
            yr[TD + t] = m;
            out[O_MASK + (size_t)b * T_ + t] = m;   // mask pass-through
        }
        for (int k = TD + T_ + tid; k < KP; k += 256) yr[k] = 0.f;

        // gather output_seq[b] = prototypes[label[b]]
        int lab = label[b];
        const float4* ps = (const float4*)(proto + (size_t)lab * TD);
        float4* od = (float4*)(out + O_OUT + (size_t)b * TD);
        for (int i = tid; i < TD / 4; i += 256) od[i] = ps[i];
        if (tid == 0) {
            out[O_IDX + b] = (float)lab;    // K=1 -> indices == label
            out[O_LAB + b] = (float)lab;
        }

        // S1 reduce
        for (int o = 16; o; o >>= 1) s1 += __shfl_xor_sync(0xffffffffu, s1, o);
        if ((tid & 31) == 0) red[tid >> 5] = s1;
        __syncthreads();
        if (tid < 32) {
            float v = (tid < 8) ? red[tid] : 0.f;
            for (int o = 4; o; o >>= 1) v += __shfl_xor_sync(0xffffffffu, v, o);
            if (tid == 0) g_S1[b] = v;
        }
    } else {
        // ---- proto_count ----
        __shared__ int cnt[C_];
        if (tid < C_) cnt[tid] = 0;
        __syncthreads();
        int lab = label[tid];            // 256 threads == B_
        atomicAdd(&cnt[lab], 1);
        __syncthreads();
        if (tid < C_) out[O_PC + tid] = pcin[tid] + (float)cnt[tid];
    }
}

// ---------------------------------------------------------------------------
// Kernel B: split-K GEMM with packed f32x2 FMAs.
// grid = (16 m-tiles, 2 c-tiles, SPLITK). 256 threads = 8 warps.
// Warp w handles c in [cTile*32 + 4w, +4), 16 b-rows; lanes split k (4 each).
// ---------------------------------------------------------------------------
__global__ void __launch_bounds__(256, 1) gemm_kernel() {
    int warp = threadIdx.x >> 5, lane = threadIdx.x & 31;
    int bm0 = blockIdx.x * 16;
    int c0  = blockIdx.y * 32 + warp * 4;
    int kz  = blockIdx.z * KCH;

    unsigned long long acc[16][4];
    #pragma unroll
    for (int i = 0; i < 16; i++)
        #pragma unroll
        for (int j = 0; j < 4; j++) acc[i][j] = 0ull;

    const float* Yb = g_Y + (size_t)bm0 * KP;
    const float* Pb = g_P + (size_t)c0 * KP;

    #pragma unroll
    for (int s = 0; s < KCH / 128; s++) {
        int k = kz + s * 128 + lane * 4;
        ulonglong2 pv[4];
        #pragma unroll
        for (int j = 0; j < 4; j++)
            pv[j] = *(const ulonglong2*)(Pb + (size_t)j * KP + k);
        #pragma unroll
        for (int i = 0; i < 16; i++) {
            ulonglong2 yv = *(const ulonglong2*)(Yb + (size_t)i * KP + k);
            #pragma unroll
            for (int j = 0; j < 4; j++) {
                asm("fma.rn.f32x2 %0, %1, %2, %0;"
                    : "+l"(acc[i][j]) : "l"(yv.x), "l"(pv[j].x));
                asm("fma.rn.f32x2 %0, %1, %2, %0;"
                    : "+l"(acc[i][j]) : "l"(yv.y), "l"(pv[j].y));
            }
        }
    }

    float* part = g_part + (size_t)blockIdx.z * B_ * C_;
    #pragma unroll
    for (int i = 0; i < 16; i++) {
        #pragma unroll
        for (int j = 0; j < 4; j++) {
            float2 f = *reinterpret_cast<float2*>(&acc[i][j]);
            float v = f.x + f.y;
            for (int o = 16; o; o >>= 1) v += __shfl_xor_sync(0xffffffffu, v, o);
            if (lane == 0) part[(bm0 + i) * C_ + c0 + j] = v;
        }
    }
}

// ---------------------------------------------------------------------------
// Kernel C: loss[b][c] = S1[b] - 2*sum_s part[s][b][c]  (fixed order)
// ---------------------------------------------------------------------------
__global__ void loss_kernel(float* __restrict__ out) {
    int idx = blockIdx.x * blockDim.x + threadIdx.x;   // < B_*C_
    int b = idx >> 6;
    float s = 0.f;
    #pragma unroll
    for (int sp = 0; sp < SPLITK; sp++) s += g_part[(sp * B_ + b) * C_ + (idx & 63)];
    out[O_LOSS + idx] = g_S1[b] - 2.f * s;
}

// ---------------------------------------------------------------------------
extern "C" void kernel_launch(void* const* d_in, const int* in_sizes, int n_in,
                              void* d_out, int out_size) {
    const float* input_seq  = (const float*)d_in[0];
    const int*   label      = (const int*)  d_in[1];
    const float* mask       = (const float*)d_in[2];
    const float* prototypes = (const float*)d_in[3];
    const float* weights    = (const float*)d_in[4];
    const float* protocount = (const float*)d_in[5];
    float* out = (float*)d_out;

    sp_kernel<<<32, 128>>>(weights);
    prep_kernel<<<C_ + B_ + 1, 256>>>(input_seq, label, mask, prototypes,
                                      protocount, out);
    gemm_kernel<<<dim3(16, 2, SPLITK), 256>>>();
    loss_kernel<<<(B_ * C_) / 256, 256>>>(out);
}